// round 11
// baseline (speedup 1.0000x reference)
#include <cuda_runtime.h>
#include <stdint.h>

#define NPTS 500000
#define KK 27

// Scratch (allocation-free rule: __device__ globals)
__device__ float g_h0 [NPTS * 32];   // relu(x@W00+b00)
__device__ float g_h0c[NPTS * 32];   // relu(conv3(h0,W01)+b01)
__device__ float g_h1 [NPTS * 32];   // relu(conv3(x,W10)+b10)

// Permuted tf32 weights, fragment-ordered (R5 layout):
//   slot s = ((k*PAIRS + pr)*NTS + nt)*32 + lane, each slot = uint4
//   {W[k][pr*16+four][col], W[k][pr*16+four+4][col],
//    W[k][pr*16+four+8][col], W[k][pr*16+four+12][col]}
#define WP10_OFF 0
#define WP01_OFF 27648
#define WP11_OFF (27648 + 6912)
#define WP00_OFF (27648 + 6912 + 13824)
#define WP02_OFF (27648 + 6912 + 13824 + 1024)
__device__ uint4 g_wperm[27648 + 6912 + 13824 + 1024 + 512];

// ---------------------------------------------------------------------------
__device__ __forceinline__ uint32_t f2tf32(float v) {
    uint32_t r;
    asm("cvt.rna.tf32.f32 %0, %1;" : "=r"(r) : "f"(v));
    return r;
}

__device__ __forceinline__ void mma_16n8k8(float* c, uint32_t a0, uint32_t a1,
                                           uint32_t a2, uint32_t a3,
                                           uint32_t b0, uint32_t b1) {
    asm volatile(
        "mma.sync.aligned.m16n8k8.row.col.f32.tf32.tf32.f32 "
        "{%0,%1,%2,%3}, {%4,%5,%6,%7}, {%8,%9}, {%0,%1,%2,%3};"
        : "+f"(c[0]), "+f"(c[1]), "+f"(c[2]), "+f"(c[3])
        : "r"(a0), "r"(a1), "r"(a2), "r"(a3), "r"(b0), "r"(b1));
}

// ---------------------------------------------------------------------------
// Weight permutation prep (R5 layout, KKT taps).
// ---------------------------------------------------------------------------
template <int CIN, int COUT, int KKT>
__global__ void k_permW(const float* __restrict__ W, uint4* __restrict__ dst)
{
    const int PAIRS = CIN / 16, NTS = COUT / 8;
    const int total = KKT * PAIRS * NTS * 32;
    const int s = blockIdx.x * 256 + threadIdx.x;
    if (s >= total) return;
    const int lane = s & 31;
    int t = s >> 5;
    const int nt = t % NTS; t /= NTS;
    const int pr = t % PAIRS; t /= PAIRS;
    const int k = t;
    const int four = lane & 3, grp = lane >> 2;
    const int col = nt * 8 + grp;
    const int r0 = pr * 16 + four;
    const size_t base = (size_t)k * CIN * COUT + col;
    uint4 v;
    v.x = f2tf32(W[base + (size_t)(r0)      * COUT]);
    v.y = f2tf32(W[base + (size_t)(r0 + 4)  * COUT]);
    v.z = f2tf32(W[base + (size_t)(r0 + 8)  * COUT]);
    v.w = f2tf32(W[base + (size_t)(r0 + 12) * COUT]);
    dst[s] = v;
}

// ---------------------------------------------------------------------------
// Unified sparse-conv GEMM via mma.sync tf32 (R8 A-path, R9 B double-buffer).
// Block: 256 threads = 8 warps; 256 points/block; warp owns 32 points.
// GATHER=1: 27-tap gather conv.  GATHER=0: 1x1 (KT=1).
// MODE 0: out[N,COUT] = relu(acc + b)
// MODE 1: out[N,128] cols [64,128) = acc + b + x[:,64:128)   (COUT=64)
// MODE 2: out[N,128] cols [0,64)   = acc + b + x[:,0:64)     (COUT=64)
// ---------------------------------------------------------------------------
template <int CIN, int COUT, int MODE, int GATHER>
__global__ __launch_bounds__(256) void k_conv_mma(
    const float* __restrict__ f, const int* __restrict__ nbr,
    const int* __restrict__ mask, const uint4* __restrict__ Wp,
    const float* __restrict__ b, const float* __restrict__ x,
    float* __restrict__ out)
{
    const int PAIRS = CIN / 16, NTS = COUT / 8;
    const int KT = GATHER ? KK : 1;
    const int slabN = PAIRS * NTS * 32;        // uint4 per k
    const int NPER  = slabN / 256;             // uint4 per thread per slab
    __shared__ int   midx[GATHER ? 256 * KK : 8];
    __shared__ uint4 Bs4[2][PAIRS * NTS * 32 > 256 ? PAIRS * NTS * 32 : 256];
    __shared__ float bs[COUT];

    const int tid  = threadIdx.x;
    const int warp = tid >> 5;
    const int lane = tid & 31;
    const int grp  = lane >> 2;
    const int four = lane & 3;

    if (tid < COUT) bs[tid] = b[tid];

    const int pbase = blockIdx.x * 256;
    if (GATHER) {
        for (int i = tid; i < 256 * KK; i += 256) {
            const int p = pbase + i / KK;
            int v = -1;
            if (p < NPTS) {
                const size_t g = (size_t)p * KK + (i % KK);
                if (mask[g] != 0) v = nbr[g];
            }
            midx[i] = v;
        }
    }

    const int lr = warp * 32 + grp;            // rows lr+{0,8,16,24}

    float acc0[NTS][4], acc1[NTS][4];
#pragma unroll
    for (int nt = 0; nt < NTS; nt++)
#pragma unroll
        for (int j = 0; j < 4; j++) { acc0[nt][j] = 0.f; acc1[nt][j] = 0.f; }

    // prefetch slab k=0
    uint4 pre[NPER];
#pragma unroll
    for (int i = 0; i < NPER; i++) pre[i] = Wp[i * 256 + tid];

    for (int k = 0; k < KT; k++) {
        const int s = k & 1;
        // publish prefetched slab k into buffer s
#pragma unroll
        for (int i = 0; i < NPER; i++) Bs4[s][i * 256 + tid] = pre[i];
        __syncthreads();
        // prefetch slab k+1 (clamped)
        {
            const int kn = (k + 1 < KT) ? (k + 1) : k;
#pragma unroll
            for (int i = 0; i < NPER; i++)
                pre[i] = Wp[(size_t)kn * slabN + i * 256 + tid];
        }

        int idx[4];
#pragma unroll
        for (int r = 0; r < 4; r++) {
            if (GATHER) {
                idx[r] = midx[(lr + r * 8) * KK + k];
            } else {
                const int p = pbase + lr + r * 8;
                idx[r] = (p < NPTS) ? p : (NPTS - 1);   // clamp; store guarded later
            }
        }
        const float* rows[4];
#pragma unroll
        for (int r = 0; r < 4; r++)
            rows[r] = f + (size_t)(idx[r] < 0 ? 0 : idx[r]) * CIN;

#pragma unroll
        for (int pr = 0; pr < PAIRS; pr++) {
            uint32_t A[4][4];   // [row][elem: four, four+4, four+8, four+12]
#pragma unroll
            for (int r = 0; r < 4; r++) {
                if (!GATHER || idx[r] >= 0) {
                    const float* rp = rows[r] + pr * 16 + four;
                    A[r][0] = f2tf32(__ldg(rp));
                    A[r][1] = f2tf32(__ldg(rp + 4));
                    A[r][2] = f2tf32(__ldg(rp + 8));
                    A[r][3] = f2tf32(__ldg(rp + 12));
                } else {
                    A[r][0] = A[r][1] = A[r][2] = A[r][3] = 0u;
                }
            }
#pragma unroll
            for (int nt = 0; nt < NTS; nt++) {
                const uint4 B = Bs4[s][(pr * NTS + nt) * 32 + lane];
                mma_16n8k8(acc0[nt], A[0][0], A[1][0], A[0][1], A[1][1], B.x, B.y);
                mma_16n8k8(acc0[nt], A[0][2], A[1][2], A[0][3], A[1][3], B.z, B.w);
                mma_16n8k8(acc1[nt], A[2][0], A[3][0], A[2][1], A[3][1], B.x, B.y);
                mma_16n8k8(acc1[nt], A[2][2], A[3][2], A[2][3], A[3][3], B.z, B.w);
            }
        }
    }

    // epilogue: acc0 -> rows lr, lr+8 ; acc1 -> rows lr+16, lr+24
#pragma unroll
    for (int t = 0; t < 2; t++) {
#pragma unroll
        for (int half = 0; half < 2; half++) {
            const int p = pbase + lr + t * 16 + half * 8;
            if (p >= NPTS) continue;
#pragma unroll
            for (int nt = 0; nt < NTS; nt++) {
                const float c0 = (t == 0) ? acc0[nt][half * 2]     : acc1[nt][half * 2];
                const float c1 = (t == 0) ? acc0[nt][half * 2 + 1] : acc1[nt][half * 2 + 1];
                const int col = nt * 8 + 2 * four;
                if (MODE == 0) {
                    float2 v = {fmaxf(c0 + bs[col], 0.f), fmaxf(c1 + bs[col + 1], 0.f)};
                    *reinterpret_cast<float2*>(out + (size_t)p * COUT + col) = v;
                } else {
                    const int oc = (MODE == 1) ? (64 + col) : col;
                    const size_t a = (size_t)p * 128 + oc;
                    float2 xr = *reinterpret_cast<const float2*>(x + a);
                    float2 v = {c0 + bs[col] + xr.x, c1 + bs[col + 1] + xr.y};
                    *reinterpret_cast<float2*>(out + a) = v;
                }
            }
        }
    }
}

// ---------------------------------------------------------------------------
extern "C" void kernel_launch(void* const* d_in, const int* in_sizes, int n_in,
                              void* d_out, int out_size)
{
    const float* x    = (const float*)d_in[0];
    const int*   nbr  = (const int*)  d_in[1];
    const int*   mask = (const int*)  d_in[2];   // bool -> int32 in harness
    const float* W00  = (const float*)d_in[3];
    const float* b00  = (const float*)d_in[4];
    const float* W01  = (const float*)d_in[5];
    const float* b01  = (const float*)d_in[6];
    const float* W02  = (const float*)d_in[7];
    const float* b02  = (const float*)d_in[8];
    const float* W10  = (const float*)d_in[9];
    const float* b10  = (const float*)d_in[10];
    const float* W11  = (const float*)d_in[11];
    const float* b11  = (const float*)d_in[12];
    float* out = (float*)d_out;

    float *h0, *h0c, *h1;
    uint4* wp;
    cudaGetSymbolAddress((void**)&h0,  g_h0);
    cudaGetSymbolAddress((void**)&h0c, g_h0c);
    cudaGetSymbolAddress((void**)&h1,  g_h1);
    cudaGetSymbolAddress((void**)&wp,  g_wperm);

    const int blocks = (NPTS + 255) / 256;

    // launches 0..2: permutations needed by the big conv + its successors
    k_permW<128, 32, KK><<<(27648 + 255) / 256, 256>>>(W10, wp + WP10_OFF);
    k_permW< 32, 32, KK><<<( 6912 + 255) / 256, 256>>>(W01, wp + WP01_OFF);
    k_permW< 32, 64, KK><<<(13824 + 255) / 256, 256>>>(W11, wp + WP11_OFF);

    // launch 3 (ncu capture slot): branch 1 heavy conv3 -> relu
    k_conv_mma<128, 32, 0, 1><<<blocks, 256>>>(x, nbr, mask, wp + WP10_OFF, b10, nullptr, h1);

    // remaining prep
    k_permW<128, 32,  1><<<( 1024 + 255) / 256, 256>>>(W00, wp + WP00_OFF);
    k_permW< 32, 64,  1><<<(  512 + 255) / 256, 256>>>(W02, wp + WP02_OFF);

    // branch 0: 1x1 -> relu
    k_conv_mma<128, 32, 0, 0><<<blocks, 256>>>(x, nullptr, nullptr, wp + WP00_OFF, b00, nullptr, h0);
    // branch 0: 3x3 -> relu
    k_conv_mma<32, 32, 0, 1><<<blocks, 256>>>(h0, nbr, mask, wp + WP01_OFF, b01, nullptr, h0c);
    // branch 0 tail: 1x1 + bias + residual -> out[:, 0:64)
    k_conv_mma<32, 64, 2, 0><<<blocks, 256>>>(h0c, nullptr, nullptr, wp + WP02_OFF, b02, x, out);
    // branch 1 tail: 3x3 + bias + residual -> out[:, 64:128)
    k_conv_mma<32, 64, 1, 1><<<blocks, 256>>>(h1, nbr, mask, wp + WP11_OFF, b11, x, out);
}

// round 12
// speedup vs baseline: 1.4628x; 1.4628x over previous
#include <cuda_runtime.h>
#include <stdint.h>

#define NPTS 500000
#define KK 27

// Scratch (allocation-free rule: __device__ globals)
__device__ float g_h0 [NPTS * 32];
__device__ float g_h0c[NPTS * 32];
__device__ float g_h1 [NPTS * 32];
__device__ int   g_midxT[(size_t)KK * NPTS];   // transposed masked idx: [k][p]

// Permuted tf32 weights, fragment-ordered (R5 layout).
#define WP10_OFF 0
#define WP01_OFF 27648
#define WP11_OFF (27648 + 6912)
#define WP00_OFF (27648 + 6912 + 13824)
#define WP02_OFF (27648 + 6912 + 13824 + 1024)
__device__ uint4 g_wperm[27648 + 6912 + 13824 + 1024 + 512];

// ---------------------------------------------------------------------------
__device__ __forceinline__ uint32_t f2tf32(float v) {
    uint32_t r;
    asm("cvt.rna.tf32.f32 %0, %1;" : "=r"(r) : "f"(v));
    return r;
}

__device__ __forceinline__ void mma_16n8k8(float* c, uint32_t a0, uint32_t a1,
                                           uint32_t a2, uint32_t a3,
                                           uint32_t b0, uint32_t b1) {
    asm volatile(
        "mma.sync.aligned.m16n8k8.row.col.f32.tf32.tf32.f32 "
        "{%0,%1,%2,%3}, {%4,%5,%6,%7}, {%8,%9}, {%0,%1,%2,%3};"
        : "+f"(c[0]), "+f"(c[1]), "+f"(c[2]), "+f"(c[3])
        : "r"(a0), "r"(a1), "r"(a2), "r"(a3), "r"(b0), "r"(b1));
}

// ---------------------------------------------------------------------------
// Weight permutation prep (R5 fragment layout, KKT taps).
// ---------------------------------------------------------------------------
template <int CIN, int COUT, int KKT>
__global__ void k_permW(const float* __restrict__ W, uint4* __restrict__ dst)
{
    const int PAIRS = CIN / 16, NTS = COUT / 8;
    const int total = KKT * PAIRS * NTS * 32;
    const int s = blockIdx.x * 256 + threadIdx.x;
    if (s >= total) return;
    const int lane = s & 31;
    int t = s >> 5;
    const int nt = t % NTS; t /= NTS;
    const int pr = t % PAIRS; t /= PAIRS;
    const int k = t;
    const int four = lane & 3, grp = lane >> 2;
    const int col = nt * 8 + grp;
    const int r0 = pr * 16 + four;
    const size_t base = (size_t)k * CIN * COUT + col;
    uint4 v;
    v.x = f2tf32(W[base + (size_t)(r0)      * COUT]);
    v.y = f2tf32(W[base + (size_t)(r0 + 4)  * COUT]);
    v.z = f2tf32(W[base + (size_t)(r0 + 8)  * COUT]);
    v.w = f2tf32(W[base + (size_t)(r0 + 12) * COUT]);
    dst[s] = v;
}

// ---------------------------------------------------------------------------
// Masked-neighbor transpose prep: midxT[k][p] = mask[p][k] ? nbr[p][k] : -1.
// Tile through smem so both gmem phases are coalesced.
// ---------------------------------------------------------------------------
__global__ __launch_bounds__(256) void k_midx(const int* __restrict__ nbr,
                                              const int* __restrict__ mask,
                                              int* __restrict__ midxT)
{
    __shared__ int tile[128 * KK];
    const int tid = threadIdx.x;
    const int pbase = blockIdx.x * 128;
    for (int i = tid; i < 128 * KK; i += 256) {
        const int p = pbase + i / KK;
        int v = -1;
        if (p < NPTS) {
            const size_t g = (size_t)pbase * KK + i;
            if (mask[g] != 0) v = nbr[g];
        }
        tile[i] = v;
    }
    __syncthreads();
    for (int i = tid; i < 128 * KK; i += 256) {
        const int k = i >> 7, j = i & 127;
        if (pbase + j < NPTS)
            midxT[(size_t)k * NPTS + pbase + j] = tile[j * KK + k];
    }
}

// ---------------------------------------------------------------------------
// Unified sparse-conv GEMM via mma.sync tf32, m16 warp tiles (low-reg).
// Block: 256 threads = 8 warps; 128 points/block; warp owns 16 points
// (lane covers rows grp and grp+8 of its m16 tile).
// GATHER=1: 27-tap gather conv via midxT.  GATHER=0: 1x1 (KT=1).
// MODE 0: out[N,COUT] = relu(acc + b)
// MODE 1: out[N,128] cols [64,128) = acc + b + x[:,64:128)   (COUT=64)
// MODE 2: out[N,128] cols [0,64)   = acc + b + x[:,0:64)     (COUT=64)
// ---------------------------------------------------------------------------
template <int CIN, int COUT, int MODE, int GATHER>
__global__ __launch_bounds__(256) void k_conv_mma(
    const float* __restrict__ f, const int* __restrict__ midxT,
    const uint4* __restrict__ Wp, const float* __restrict__ b,
    const float* __restrict__ x, float* __restrict__ out)
{
    const int PAIRS = CIN / 16, NTS = COUT / 8;
    const int KT = GATHER ? KK : 1;
    const int slabN = PAIRS * NTS * 32;        // uint4 per k
    __shared__ uint4 Bs4[CIN * COUT / 4];
    __shared__ float bs[COUT];

    const int tid  = threadIdx.x;
    const int warp = tid >> 5;
    const int lane = tid & 31;
    const int grp  = lane >> 2;
    const int four = lane & 3;

    if (tid < COUT) bs[tid] = b[tid];

    const int pbase = blockIdx.x * 128;
    const int p0 = pbase + warp * 16 + grp;    // lane's rows: p0, p0+8

    float acc[NTS][4];
#pragma unroll
    for (int nt = 0; nt < NTS; nt++)
#pragma unroll
        for (int j = 0; j < 4; j++) acc[nt][j] = 0.f;

    for (int k = 0; k < KT; k++) {
        __syncthreads();
        for (int i = tid; i < slabN; i += 256)
            Bs4[i] = Wp[(size_t)k * slabN + i];
        __syncthreads();

        int i0, i1;
        if (GATHER) {
            const int* mt = midxT + (size_t)k * NPTS;
            i0 = (p0     < NPTS) ? __ldg(mt + p0)     : -1;
            i1 = (p0 + 8 < NPTS) ? __ldg(mt + p0 + 8) : -1;
        } else {
            i0 = (p0     < NPTS) ? p0     : NPTS - 1;   // clamp; store guarded later
            i1 = (p0 + 8 < NPTS) ? p0 + 8 : NPTS - 1;
        }
        const float* r0 = f + (size_t)(i0 < 0 ? 0 : i0) * CIN;
        const float* r1 = f + (size_t)(i1 < 0 ? 0 : i1) * CIN;

#pragma unroll
        for (int pr = 0; pr < PAIRS; pr++) {
            uint32_t A0[4], A1[4];   // elems: four, four+4, four+8, four+12
            if (!GATHER || i0 >= 0) {
                const float* rp = r0 + pr * 16 + four;
                A0[0] = f2tf32(__ldg(rp));
                A0[1] = f2tf32(__ldg(rp + 4));
                A0[2] = f2tf32(__ldg(rp + 8));
                A0[3] = f2tf32(__ldg(rp + 12));
            } else {
                A0[0] = A0[1] = A0[2] = A0[3] = 0u;
            }
            if (!GATHER || i1 >= 0) {
                const float* rp = r1 + pr * 16 + four;
                A1[0] = f2tf32(__ldg(rp));
                A1[1] = f2tf32(__ldg(rp + 4));
                A1[2] = f2tf32(__ldg(rp + 8));
                A1[3] = f2tf32(__ldg(rp + 12));
            } else {
                A1[0] = A1[1] = A1[2] = A1[3] = 0u;
            }
#pragma unroll
            for (int nt = 0; nt < NTS; nt++) {
                const uint4 B = Bs4[(pr * NTS + nt) * 32 + lane];
                mma_16n8k8(acc[nt], A0[0], A1[0], A0[1], A1[1], B.x, B.y);
                mma_16n8k8(acc[nt], A0[2], A1[2], A0[3], A1[3], B.z, B.w);
            }
        }
    }

    // epilogue: acc[nt][0,1] -> row p0 ; acc[nt][2,3] -> row p0+8
#pragma unroll
    for (int half = 0; half < 2; half++) {
        const int p = p0 + half * 8;
        if (p >= NPTS) continue;
#pragma unroll
        for (int nt = 0; nt < NTS; nt++) {
            const float c0 = acc[nt][half * 2];
            const float c1 = acc[nt][half * 2 + 1];
            const int col = nt * 8 + 2 * four;
            if (MODE == 0) {
                float2 v = {fmaxf(c0 + bs[col], 0.f), fmaxf(c1 + bs[col + 1], 0.f)};
                *reinterpret_cast<float2*>(out + (size_t)p * COUT + col) = v;
            } else {
                const int oc = (MODE == 1) ? (64 + col) : col;
                const size_t a = (size_t)p * 128 + oc;
                float2 xr = *reinterpret_cast<const float2*>(x + a);
                float2 v = {c0 + bs[col] + xr.x, c1 + bs[col + 1] + xr.y};
                *reinterpret_cast<float2*>(out + a) = v;
            }
        }
    }
}

// ---------------------------------------------------------------------------
extern "C" void kernel_launch(void* const* d_in, const int* in_sizes, int n_in,
                              void* d_out, int out_size)
{
    const float* x    = (const float*)d_in[0];
    const int*   nbr  = (const int*)  d_in[1];
    const int*   mask = (const int*)  d_in[2];   // bool -> int32 in harness
    const float* W00  = (const float*)d_in[3];
    const float* b00  = (const float*)d_in[4];
    const float* W01  = (const float*)d_in[5];
    const float* b01  = (const float*)d_in[6];
    const float* W02  = (const float*)d_in[7];
    const float* b02  = (const float*)d_in[8];
    const float* W10  = (const float*)d_in[9];
    const float* b10  = (const float*)d_in[10];
    const float* W11  = (const float*)d_in[11];
    const float* b11  = (const float*)d_in[12];
    float* out = (float*)d_out;

    float *h0, *h0c, *h1;
    int* midxT;
    uint4* wp;
    cudaGetSymbolAddress((void**)&h0,    g_h0);
    cudaGetSymbolAddress((void**)&h0c,   g_h0c);
    cudaGetSymbolAddress((void**)&h1,    g_h1);
    cudaGetSymbolAddress((void**)&midxT, g_midxT);
    cudaGetSymbolAddress((void**)&wp,    g_wperm);

    const int blocks  = (NPTS + 127) / 128;   // conv kernels: 128 points/block
    const int tblocks = (NPTS + 127) / 128;   // midx transpose tiles

    // launches 0..2: prep needed by the big conv
    k_permW<128, 32, KK><<<(27648 + 255) / 256, 256>>>(W10, wp + WP10_OFF);
    k_permW< 32, 32, KK><<<( 6912 + 255) / 256, 256>>>(W01, wp + WP01_OFF);
    k_midx<<<tblocks, 256>>>(nbr, mask, midxT);

    // launch 3 (ncu capture slot): branch 1 heavy conv3 -> relu
    k_conv_mma<128, 32, 0, 1><<<blocks, 256>>>(x, midxT, wp + WP10_OFF, b10, nullptr, h1);

    // remaining prep
    k_permW< 32, 64, KK><<<(13824 + 255) / 256, 256>>>(W11, wp + WP11_OFF);
    k_permW<128, 32,  1><<<( 1024 + 255) / 256, 256>>>(W00, wp + WP00_OFF);
    k_permW< 32, 64,  1><<<(  512 + 255) / 256, 256>>>(W02, wp + WP02_OFF);

    // branch 0: 1x1 -> relu
    k_conv_mma<128, 32, 0, 0><<<blocks, 256>>>(x, nullptr, wp + WP00_OFF, b00, nullptr, h0);
    // branch 0: 3x3 -> relu
    k_conv_mma<32, 32, 0, 1><<<blocks, 256>>>(h0, midxT, wp + WP01_OFF, b01, nullptr, h0c);
    // branch 0 tail: 1x1 + bias + residual -> out[:, 0:64)
    k_conv_mma<32, 64, 2, 0><<<blocks, 256>>>(h0c, nullptr, wp + WP02_OFF, b02, x, out);
    // branch 1 tail: 3x3 + bias + residual -> out[:, 64:128)
    k_conv_mma<32, 64, 1, 1><<<blocks, 256>>>(h1, midxT, wp + WP11_OFF, b11, x, out);
}